// round 1
// baseline (speedup 1.0000x reference)
#include <cuda_runtime.h>

#define FULLMASK 0xffffffffu

static const int CH  = 64;
static const int HWX = 65536;   // 256*256
static const int WD  = 256;

// Scratch (device globals are the sanctioned scratch mechanism)
__device__ float g_q[16777216];   // [B*C][HW]
__device__ float g_v[16777216];   // [B*C][HW]
__device__ float g_k[67108864];   // [N*B*C][HW]
__device__ float g_ps[16777216];  // [B*C][W][W]  (sum over n of space softmax)

__device__ __forceinline__ float warp_max(float v) {
#pragma unroll
  for (int o = 16; o > 0; o >>= 1) v = fmaxf(v, __shfl_xor_sync(FULLMASK, v, o));
  return v;
}
__device__ __forceinline__ float warp_sum(float v) {
#pragma unroll
  for (int o = 16; o > 0; o >>= 1) v += __shfl_xor_sync(FULLMASK, v, o);
  return v;
}

// ---------------------------------------------------------------------------
// conv1x1: y[pb][oc][px] = sum_i w[oc][i] * x[pb][i][px] + b[oc]
// grid: (HW/64, P) ; 256 threads ; each thread: 4 oc x 4 px (x2 outputs if DUAL)
// ---------------------------------------------------------------------------
template <bool DUAL>
__global__ __launch_bounds__(256, 1) void conv1x1_kernel(
    const float* __restrict__ x,
    const float* __restrict__ w1, const float* __restrict__ b1, float* __restrict__ y1,
    const float* __restrict__ w2, const float* __restrict__ b2, float* __restrict__ y2)
{
  extern __shared__ float sm[];
  float* Xs  = sm;            // [64 i][64 px]
  float* W1s = sm + 4096;     // [64 oc][64 i]
  float* W2s = sm + 8192;     // [64 oc][64 i] (DUAL only)

  const int tid = threadIdx.x;
  const int pb  = blockIdx.y;
  const int px0 = blockIdx.x * 64;
  const float* xp = x + (size_t)pb * CH * HWX;

#pragma unroll 4
  for (int idx = tid; idx < 4096; idx += 256) {
    W1s[idx] = w1[idx];
    if (DUAL) W2s[idx] = w2[idx];
    Xs[idx] = xp[(size_t)(idx >> 6) * HWX + px0 + (idx & 63)];
  }
  __syncthreads();

  const int ocg = tid >> 4;   // 0..15
  const int pxg = tid & 15;   // 0..15
  float a1[4][4] = {};
  float a2[4][4] = {};

#pragma unroll 8
  for (int i = 0; i < 64; i++) {
    float4 xv = *(const float4*)&Xs[i * 64 + pxg * 4];
#pragma unroll
    for (int r = 0; r < 4; r++) {
      float wv = W1s[(ocg * 4 + r) * 64 + i];
      a1[r][0] += wv * xv.x; a1[r][1] += wv * xv.y;
      a1[r][2] += wv * xv.z; a1[r][3] += wv * xv.w;
      if (DUAL) {
        float w2v = W2s[(ocg * 4 + r) * 64 + i];
        a2[r][0] += w2v * xv.x; a2[r][1] += w2v * xv.y;
        a2[r][2] += w2v * xv.z; a2[r][3] += w2v * xv.w;
      }
    }
  }

#pragma unroll
  for (int r = 0; r < 4; r++) {
    int oc = ocg * 4 + r;
    size_t base = (size_t)pb * CH * HWX + (size_t)oc * HWX + px0 + pxg * 4;
    float bb = b1[oc];
    float4 o1 = make_float4(a1[r][0] + bb, a1[r][1] + bb, a1[r][2] + bb, a1[r][3] + bb);
    *(float4*)&y1[base] = o1;
    if (DUAL) {
      float bb2 = b2[oc];
      float4 o2 = make_float4(a2[r][0] + bb2, a2[r][1] + bb2, a2[r][2] + bb2, a2[r][3] + bb2);
      *(float4*)&y2[base] = o2;
    }
  }
}

// ---------------------------------------------------------------------------
// Fused time attention: per (bc, 64-row h block):
//   Pacc = sum_n rowsoftmax(Q_blk K_n^T / 16)   (softmax rows live in one warp)
//   out_blk = main_blk + Pacc @ V
// grid: (256, 4) ; 256 threads ; thread microtile 8x8
// smem: Qs[64][256] + KV[64][260] + Ps[64][256]  = 197632 B
// ---------------------------------------------------------------------------
__global__ __launch_bounds__(256, 1) void time_attn_kernel(
    const float* __restrict__ mainx, float* __restrict__ out)
{
  extern __shared__ float sm[];
  float* Qs = sm;              // 16384 floats  [64 h][256 w]
  float* KV = sm + 16384;      // 16640 floats  [64 w][260] (K^T tile) / [64 g][256 w] (V tile)
  float* Ps = sm + 33024;      // 16384 floats  [64 h][256 g]

  const int bc  = blockIdx.x;
  const int h0  = blockIdx.y * 64;
  const int tid = threadIdx.x;
  const int th  = tid >> 5;    // 0..7  (row group)
  const int tg  = tid & 31;    // 0..31 (col group)

  const float* qpl = g_q + (size_t)bc * HWX;
  const float* vpl = g_v + (size_t)bc * HWX;

  // Q block (contiguous rows)
#pragma unroll 4
  for (int idx = tid; idx < 16384; idx += 256) Qs[idx] = qpl[h0 * WD + idx];

  float Pacc[8][8];
#pragma unroll
  for (int r = 0; r < 8; r++)
#pragma unroll
    for (int j = 0; j < 8; j++) Pacc[r][j] = 0.f;

  const float scale = 0.0625f;  // 1/sqrt(256)

  for (int n = 0; n < 4; n++) {
    const float* kpl = g_k + ((size_t)n * 256 + bc) * HWX;
    float Sacc[8][8];
#pragma unroll
    for (int r = 0; r < 8; r++)
#pragma unroll
      for (int j = 0; j < 8; j++) Sacc[r][j] = 0.f;

    for (int wt = 0; wt < 4; wt++) {
      __syncthreads();
      const int w0 = wt * 64;
      // load K tile transposed: KV[w][g] = k[g][w0+w]
#pragma unroll 4
      for (int idx = tid; idx < 16384; idx += 256) {
        int g = idx >> 6, w = idx & 63;
        KV[w * 260 + g] = kpl[g * WD + w0 + w];
      }
      __syncthreads();
#pragma unroll 4
      for (int w = 0; w < 64; w++) {
        float qv[8];
#pragma unroll
        for (int r = 0; r < 8; r++) qv[r] = Qs[(th * 8 + r) * WD + w0 + w];
        float4 k0 = *(const float4*)&KV[w * 260 + tg * 8];
        float4 k1 = *(const float4*)&KV[w * 260 + tg * 8 + 4];
        float kv[8] = {k0.x, k0.y, k0.z, k0.w, k1.x, k1.y, k1.z, k1.w};
#pragma unroll
        for (int r = 0; r < 8; r++)
#pragma unroll
          for (int j = 0; j < 8; j++) Sacc[r][j] += qv[r] * kv[j];
      }
    }
    // per-row softmax across the warp (row h -> lanes tg, 8 vals/lane)
#pragma unroll
    for (int r = 0; r < 8; r++) {
      float m = -1e30f;
#pragma unroll
      for (int j = 0; j < 8; j++) { Sacc[r][j] *= scale; m = fmaxf(m, Sacc[r][j]); }
      m = warp_max(m);
      float l = 0.f;
#pragma unroll
      for (int j = 0; j < 8; j++) { Sacc[r][j] = __expf(Sacc[r][j] - m); l += Sacc[r][j]; }
      l = warp_sum(l);
      float inv = 1.0f / l;
#pragma unroll
      for (int j = 0; j < 8; j++) Pacc[r][j] += Sacc[r][j] * inv;
    }
  }

  // Pacc -> smem
#pragma unroll
  for (int r = 0; r < 8; r++) {
    *(float4*)&Ps[(th * 8 + r) * WD + tg * 8]     = make_float4(Pacc[r][0], Pacc[r][1], Pacc[r][2], Pacc[r][3]);
    *(float4*)&Ps[(th * 8 + r) * WD + tg * 8 + 4] = make_float4(Pacc[r][4], Pacc[r][5], Pacc[r][6], Pacc[r][7]);
  }

  // ctx: O = Pacc @ V
  float Oacc[8][8];
#pragma unroll
  for (int r = 0; r < 8; r++)
#pragma unroll
    for (int j = 0; j < 8; j++) Oacc[r][j] = 0.f;

  for (int gt = 0; gt < 4; gt++) {
    __syncthreads();
    const int g0 = gt * 64;
#pragma unroll 4
    for (int idx = tid; idx < 16384; idx += 256) KV[idx] = vpl[g0 * WD + idx];
    __syncthreads();
#pragma unroll 4
    for (int g = 0; g < 64; g++) {
      float pv[8];
#pragma unroll
      for (int r = 0; r < 8; r++) pv[r] = Ps[(th * 8 + r) * WD + g0 + g];
      float4 v0 = *(const float4*)&KV[g * WD + tg * 8];
      float4 v1 = *(const float4*)&KV[g * WD + tg * 8 + 4];
      float vv[8] = {v0.x, v0.y, v0.z, v0.w, v1.x, v1.y, v1.z, v1.w};
#pragma unroll
      for (int r = 0; r < 8; r++)
#pragma unroll
        for (int j = 0; j < 8; j++) Oacc[r][j] += pv[r] * vv[j];
    }
  }

  const float* mpl = mainx + (size_t)bc * HWX;
  float* opl = out + (size_t)bc * HWX;
#pragma unroll
  for (int r = 0; r < 8; r++) {
    int row = h0 + th * 8 + r;
    float4 m0 = *(const float4*)&mpl[row * WD + tg * 8];
    float4 m1 = *(const float4*)&mpl[row * WD + tg * 8 + 4];
    float4 o0 = make_float4(m0.x + Oacc[r][0], m0.y + Oacc[r][1], m0.z + Oacc[r][2], m0.w + Oacc[r][3]);
    float4 o1 = make_float4(m1.x + Oacc[r][4], m1.y + Oacc[r][5], m1.z + Oacc[r][6], m1.w + Oacc[r][7]);
    *(float4*)&opl[row * WD + tg * 8]     = o0;
    *(float4*)&opl[row * WD + tg * 8 + 4] = o1;
  }
}

// ---------------------------------------------------------------------------
// Space scores: g_ps[bc][w][v] = sum_n rowsoftmax_v( (Q^T K_n)[w][v] / 16 )
// grid: (256, 4 w-blocks) ; smem: Qt[256 h][64 w] + Kt[64 h][256 v] = 131072 B
// ---------------------------------------------------------------------------
__global__ __launch_bounds__(256, 1) void space_score_kernel()
{
  extern __shared__ float sm[];
  float* Qt = sm;           // [256 h][64 w]  (Q columns w0..w0+63)
  float* Kt = sm + 16384;   // [64 h][256 v]

  const int bc  = blockIdx.x;
  const int w0  = blockIdx.y * 64;
  const int tid = threadIdx.x;
  const int th  = tid >> 5;
  const int tg  = tid & 31;

  const float* qpl = g_q + (size_t)bc * HWX;
#pragma unroll 4
  for (int idx = tid; idx < 16384; idx += 256) {
    int h = idx >> 6, wl = idx & 63;
    Qt[idx] = qpl[h * WD + w0 + wl];
  }

  float Pacc[8][8];
#pragma unroll
  for (int r = 0; r < 8; r++)
#pragma unroll
    for (int j = 0; j < 8; j++) Pacc[r][j] = 0.f;

  const float scale = 0.0625f;

  for (int n = 0; n < 4; n++) {
    const float* kpl = g_k + ((size_t)n * 256 + bc) * HWX;
    float Sacc[8][8];
#pragma unroll
    for (int r = 0; r < 8; r++)
#pragma unroll
      for (int j = 0; j < 8; j++) Sacc[r][j] = 0.f;

    for (int ht = 0; ht < 4; ht++) {
      __syncthreads();
#pragma unroll 4
      for (int idx = tid; idx < 16384; idx += 256) Kt[idx] = kpl[(ht * 64) * WD + idx];
      __syncthreads();
#pragma unroll 4
      for (int hl = 0; hl < 64; hl++) {
        float qv[8];
#pragma unroll
        for (int r = 0; r < 8; r++) qv[r] = Qt[(ht * 64 + hl) * 64 + th * 8 + r];
        float4 k0 = *(const float4*)&Kt[hl * WD + tg * 8];
        float4 k1 = *(const float4*)&Kt[hl * WD + tg * 8 + 4];
        float kv[8] = {k0.x, k0.y, k0.z, k0.w, k1.x, k1.y, k1.z, k1.w};
#pragma unroll
        for (int r = 0; r < 8; r++)
#pragma unroll
          for (int j = 0; j < 8; j++) Sacc[r][j] += qv[r] * kv[j];
      }
    }
#pragma unroll
    for (int r = 0; r < 8; r++) {
      float m = -1e30f;
#pragma unroll
      for (int j = 0; j < 8; j++) { Sacc[r][j] *= scale; m = fmaxf(m, Sacc[r][j]); }
      m = warp_max(m);
      float l = 0.f;
#pragma unroll
      for (int j = 0; j < 8; j++) { Sacc[r][j] = __expf(Sacc[r][j] - m); l += Sacc[r][j]; }
      l = warp_sum(l);
      float inv = 1.0f / l;
#pragma unroll
      for (int j = 0; j < 8; j++) Pacc[r][j] += Sacc[r][j] * inv;
    }
  }

  float* ppl = g_ps + (size_t)bc * HWX;
#pragma unroll
  for (int r = 0; r < 8; r++) {
    int row = w0 + th * 8 + r;
    *(float4*)&ppl[row * WD + tg * 8]     = make_float4(Pacc[r][0], Pacc[r][1], Pacc[r][2], Pacc[r][3]);
    *(float4*)&ppl[row * WD + tg * 8 + 4] = make_float4(Pacc[r][4], Pacc[r][5], Pacc[r][6], Pacc[r][7]);
  }
}

// ---------------------------------------------------------------------------
// Space ctx: out[bc][h][v] += sum_w v[h][w] * g_ps[bc][w][v]
// grid: (256, 4 h-blocks) ; smem: Vt[64][256] + Pt[64][256] = 131072 B
// ---------------------------------------------------------------------------
__global__ __launch_bounds__(256, 1) void space_ctx_kernel(float* __restrict__ out)
{
  extern __shared__ float sm[];
  float* Vt = sm;           // [64 h][256 w]
  float* Pt = sm + 16384;   // [64 w][256 v]

  const int bc  = blockIdx.x;
  const int h0  = blockIdx.y * 64;
  const int tid = threadIdx.x;
  const int th  = tid >> 5;
  const int tg  = tid & 31;

  const float* vpl = g_v + (size_t)bc * HWX;
  const float* ppl = g_ps + (size_t)bc * HWX;

#pragma unroll 4
  for (int idx = tid; idx < 16384; idx += 256) Vt[idx] = vpl[h0 * WD + idx];

  float Oacc[8][8];
#pragma unroll
  for (int r = 0; r < 8; r++)
#pragma unroll
    for (int j = 0; j < 8; j++) Oacc[r][j] = 0.f;

  for (int wt = 0; wt < 4; wt++) {
    __syncthreads();
#pragma unroll 4
    for (int idx = tid; idx < 16384; idx += 256) Pt[idx] = ppl[(wt * 64) * WD + idx];
    __syncthreads();
#pragma unroll 4
    for (int wl = 0; wl < 64; wl++) {
      float vv[8];
#pragma unroll
      for (int r = 0; r < 8; r++) vv[r] = Vt[(th * 8 + r) * WD + wt * 64 + wl];
      float4 p0 = *(const float4*)&Pt[wl * WD + tg * 8];
      float4 p1 = *(const float4*)&Pt[wl * WD + tg * 8 + 4];
      float pv[8] = {p0.x, p0.y, p0.z, p0.w, p1.x, p1.y, p1.z, p1.w};
#pragma unroll
      for (int r = 0; r < 8; r++)
#pragma unroll
        for (int j = 0; j < 8; j++) Oacc[r][j] += vv[r] * pv[j];
    }
  }

  float* opl = out + (size_t)bc * HWX;
#pragma unroll
  for (int r = 0; r < 8; r++) {
    int row = h0 + th * 8 + r;
    float4 o0 = *(const float4*)&opl[row * WD + tg * 8];
    float4 o1 = *(const float4*)&opl[row * WD + tg * 8 + 4];
    o0.x += Oacc[r][0]; o0.y += Oacc[r][1]; o0.z += Oacc[r][2]; o0.w += Oacc[r][3];
    o1.x += Oacc[r][4]; o1.y += Oacc[r][5]; o1.z += Oacc[r][6]; o1.w += Oacc[r][7];
    *(float4*)&opl[row * WD + tg * 8]     = o0;
    *(float4*)&opl[row * WD + tg * 8 + 4] = o1;
  }
}

// ---------------------------------------------------------------------------
extern "C" void kernel_launch(void* const* d_in, const int* in_sizes, int n_in,
                              void* d_out, int out_size)
{
  (void)in_sizes; (void)n_in; (void)out_size;
  const float* mainx  = (const float*)d_in[0];
  const float* assist = (const float*)d_in[1];
  const float* wq = (const float*)d_in[2];
  const float* bq = (const float*)d_in[3];
  const float* wk = (const float*)d_in[4];
  const float* bk = (const float*)d_in[5];
  const float* wv = (const float*)d_in[6];
  const float* bv = (const float*)d_in[7];
  float* out = (float*)d_out;

  float *qp, *vp, *kp;
  cudaGetSymbolAddress((void**)&qp, g_q);
  cudaGetSymbolAddress((void**)&vp, g_v);
  cudaGetSymbolAddress((void**)&kp, g_k);

  cudaFuncSetAttribute(conv1x1_kernel<true>,  cudaFuncAttributeMaxDynamicSharedMemorySize, 49152);
  cudaFuncSetAttribute(conv1x1_kernel<false>, cudaFuncAttributeMaxDynamicSharedMemorySize, 32768);
  cudaFuncSetAttribute(time_attn_kernel,      cudaFuncAttributeMaxDynamicSharedMemorySize, 197632);
  cudaFuncSetAttribute(space_score_kernel,    cudaFuncAttributeMaxDynamicSharedMemorySize, 131072);
  cudaFuncSetAttribute(space_ctx_kernel,      cudaFuncAttributeMaxDynamicSharedMemorySize, 131072);

  // q, v from main (fused); k from assist
  conv1x1_kernel<true><<<dim3(1024, 4), 256, 49152>>>(mainx, wq, bq, qp, wv, bv, vp);
  conv1x1_kernel<false><<<dim3(1024, 16), 256, 32768>>>(assist, wk, bk, kp,
                                                        (const float*)0, (const float*)0, (float*)0);
  // out = main + (sum_n P_t,n) @ V
  time_attn_kernel<<<dim3(256, 4), 256, 197632>>>(mainx, out);
  // g_ps = sum_n P_s,n ; out += V @ g_ps
  space_score_kernel<<<dim3(256, 4), 256, 131072>>>();
  space_ctx_kernel<<<dim3(256, 4), 256, 131072>>>(out);
}